// round 16
// baseline (speedup 1.0000x reference)
#include <cuda_runtime.h>
#include <cuda_fp16.h>
#include <cstdint>
#include <cstddef>

#define D 128
#define MAXN 50000
#define MAXE 600064
#define SCAN_B 256

// ---- scratch (allocation-free: __device__ globals) ----
__device__ int    g_cnt_out[MAXN];
__device__ int    g_cnt_in[MAXN];
__device__ float  g_norm_src[MAXN];
__device__ float  g_norm_dst[MAXN];
__device__ int    g_row_start[MAXN];
__device__ int    g_occ[MAXE];                 // per-edge occurrence index within dst bucket
__device__ int    g_sorted_src[MAXE];
__device__ __half g_hf16[(size_t)MAXN * D];    // fp16 gather operand, PRE-SCALED by norm_src
__device__ __half g_agg16[(size_t)MAXN * D];   // fp16 aggregation buffer (ndst-scaled)
__device__ __half g_w1t[D * D];                // W1^T fp16 [col][k]
__device__ __half g_w2t[D * D];                // W2^T fp16 [col][k]

// ---- merged init: blocks [0,nblkN) zero counters; blocks [nblkN,nblkN+32) transpose W ----
__global__ void k_init(int* __restrict__ cnt_out, int* __restrict__ cnt_in, int N, int nblkN,
                       const float* __restrict__ W1, const float* __restrict__ W2,
                       __half* __restrict__ W1t, __half* __restrict__ W2t) {
    int b = blockIdx.x;
    int tid = threadIdx.x;
    if (b < nblkN) {
        int i = b * 256 + tid;
        if (i < N) { cnt_out[i] = 0; cnt_in[i] = 0; }
        return;
    }
    __shared__ float tile[32][33];
    int bb = b - nblkN;
    int z = bb >> 4, y = (bb >> 2) & 3, x = bb & 3;
    const float* W = z ? W2 : W1;
    __half* Wt = z ? W2t : W1t;
    int k0 = x * 32, c0 = y * 32;
    int tx = tid & 31, ty = tid >> 5;   // 32 x 8
#pragma unroll
    for (int i = 0; i < 4; i++) {
        int k = ty + i * 8;
        tile[k][tx] = __ldg(&W[(size_t)(k0 + k) * D + c0 + tx]);
    }
    __syncthreads();
#pragma unroll
    for (int i = 0; i < 4; i++) {
        int c = ty + i * 8;
        Wt[(size_t)(c0 + c) * D + k0 + tx] = __float2half_rn(tile[tx][c]);
    }
}

// ---- degree histogram: 4 edges per thread (MLP 4); persists occurrence index ----
__global__ void k_hist(const int* __restrict__ src, const int* __restrict__ dst,
                       int* __restrict__ cnt_out, int* __restrict__ cnt_in,
                       int* __restrict__ occ, int E, int stride) {
    int i = blockIdx.x * blockDim.x + threadIdx.x;
#pragma unroll
    for (int k = 0; k < 4; k++) {
        int e = i + k * stride;
        if (e < E) {
            atomicAdd(&cnt_out[__ldg(&src[e])], 1);
            occ[e] = atomicAdd(&cnt_in[__ldg(&dst[e])], 1);
        }
    }
}

// ---- single-pass scan: per-block direct prefix re-read + in-block scan + norms ----
__global__ __launch_bounds__(SCAN_B)
void k_scan(const int* __restrict__ cnt_out, const int* __restrict__ cnt_in,
            int* __restrict__ row_start,
            float* __restrict__ nsrc, float* __restrict__ ndst, int N) {
    __shared__ int sh[SCAN_B];
    const int tid = threadIdx.x;
    const int b = blockIdx.x;

    int partial = 0;
    int lim = b * SCAN_B;
    for (int j = tid; j < lim; j += SCAN_B) partial += __ldg(&cnt_in[j]);
    sh[tid] = partial; __syncthreads();
#pragma unroll
    for (int off = 128; off > 0; off >>= 1) {
        if (tid < off) sh[tid] += sh[tid + off];
        __syncthreads();
    }
    int prefix = sh[0];
    __syncthreads();

    int i = b * SCAN_B + tid;
    int v = (i < N) ? __ldg(&cnt_in[i]) : 0;
    sh[tid] = v; __syncthreads();
#pragma unroll
    for (int off = 1; off < SCAN_B; off <<= 1) {
        int t = (tid >= off) ? sh[tid - off] : 0;
        __syncthreads();
        sh[tid] += t;
        __syncthreads();
    }
    if (i < N) {
        int r = prefix + sh[tid] - v;
        row_start[i] = r;
        nsrc[i] = rsqrtf(fmaxf((float)__ldg(&cnt_out[i]), 1.f));
        ndst[i] = rsqrtf(fmaxf((float)v, 1.f));
    }
}

// ---- merged: blocks [0,nblkE4) ATOMIC-FREE bucket scatter; rest: fp16 feature mirror ----
__global__ void k_bucket_f2h(const int* __restrict__ src, const int* __restrict__ dst,
                             const int* __restrict__ occ, const int* __restrict__ row_start,
                             int* __restrict__ sorted_src,
                             int E, int stride, int nblkE4,
                             const float* __restrict__ features,
                             const int* __restrict__ cnt_out,
                             __half* __restrict__ hf16, int N) {
    int b = blockIdx.x;
    int tid = threadIdx.x;
    if (b < nblkE4) {
        int i = b * blockDim.x + tid;
#pragma unroll
        for (int k = 0; k < 4; k++) {
            int e = i + k * stride;
            if (e < E) {
                int d = __ldg(&dst[e]);
                int pos = __ldg(&row_start[d]) + __ldg(&occ[e]);
                sorted_src[pos] = __ldg(&src[e]);
            }
        }
        return;
    }
    // f2h: warp per row, full parallelism
    int row = ((b - nblkE4) * blockDim.x + tid) >> 5;
    int lane = tid & 31;
    if (row >= N) return;
    float ns = rsqrtf(fmaxf((float)__ldg(&cnt_out[row]), 1.f));
    float4 v = __ldg((const float4*)(features + (size_t)row * D) + lane);
    __half2 h0 = __floats2half2_rn(v.x * ns, v.y * ns);
    __half2 h1 = __floats2half2_rn(v.z * ns, v.w * ns);
    uint2 u;
    u.x = *(uint32_t*)&h0;
    u.y = *(uint32_t*)&h1;
    *((uint2*)(hf16 + (size_t)row * D) + lane) = u;
}

// ---- add 8 halves (uint4) into 8 fp32 accumulators ----
__device__ __forceinline__ void acc_add8(float* acc, uint4 u) {
    float2 p0 = __half22float2(*(__half2*)&u.x);
    float2 p1 = __half22float2(*(__half2*)&u.y);
    float2 p2 = __half22float2(*(__half2*)&u.z);
    float2 p3 = __half22float2(*(__half2*)&u.w);
    acc[0] += p0.x; acc[1] += p0.y;
    acc[2] += p1.x; acc[3] += p1.y;
    acc[4] += p2.x; acc[5] += p2.y;
    acc[6] += p3.x; acc[7] += p3.y;
}

// ---- atomic-free aggregation: HALF-WARP per dst node; applies ndst; fp16 out ----
__global__ void k_gather16(const __half* __restrict__ hf, const int* __restrict__ sorted_src,
                           const int* __restrict__ row_start, const int* __restrict__ cnt_in,
                           const float* __restrict__ ndst, __half* __restrict__ agg, int N) {
    int n = (blockIdx.x * blockDim.x + threadIdx.x) >> 4;
    int lane = threadIdx.x & 15;
    if (n >= N) return;
    int start = __ldg(&row_start[n]);
    int cnt = __ldg(&cnt_in[n]);
    float acc[8] = {0.f, 0.f, 0.f, 0.f, 0.f, 0.f, 0.f, 0.f};
    const int* sp = sorted_src + start;
    int j = 0;
    for (; j + 4 <= cnt; j += 4) {
        int s0 = __ldg(sp + j);
        int s1 = __ldg(sp + j + 1);
        int s2 = __ldg(sp + j + 2);
        int s3 = __ldg(sp + j + 3);
        uint4 u0 = __ldg((const uint4*)(hf + (size_t)s0 * D) + lane);
        uint4 u1 = __ldg((const uint4*)(hf + (size_t)s1 * D) + lane);
        uint4 u2 = __ldg((const uint4*)(hf + (size_t)s2 * D) + lane);
        uint4 u3 = __ldg((const uint4*)(hf + (size_t)s3 * D) + lane);
        acc_add8(acc, u0); acc_add8(acc, u1); acc_add8(acc, u2); acc_add8(acc, u3);
    }
    if (j + 2 <= cnt) {
        int s0 = __ldg(sp + j);
        int s1 = __ldg(sp + j + 1);
        uint4 u0 = __ldg((const uint4*)(hf + (size_t)s0 * D) + lane);
        uint4 u1 = __ldg((const uint4*)(hf + (size_t)s1 * D) + lane);
        acc_add8(acc, u0); acc_add8(acc, u1);
        j += 2;
    }
    if (j < cnt) {
        int s = __ldg(sp + j);
        uint4 u = __ldg((const uint4*)(hf + (size_t)s * D) + lane);
        acc_add8(acc, u);
    }
    float nd = __ldg(&ndst[n]);
    __half2 h0 = __floats2half2_rn(acc[0] * nd, acc[1] * nd);
    __half2 h1 = __floats2half2_rn(acc[2] * nd, acc[3] * nd);
    __half2 h2 = __floats2half2_rn(acc[4] * nd, acc[5] * nd);
    __half2 h3 = __floats2half2_rn(acc[6] * nd, acc[7] * nd);
    uint4 o;
    o.x = *(uint32_t*)&h0; o.y = *(uint32_t*)&h1;
    o.z = *(uint32_t*)&h2; o.w = *(uint32_t*)&h3;
    *((uint4*)(agg + (size_t)n * D) + lane) = o;
}

// ---- fp16 mma m16n8k16, fp32 accumulate ----
__device__ __forceinline__ void mma_f16(float* c, uint32_t a0, uint32_t a1,
                                        uint32_t a2, uint32_t a3,
                                        uint32_t b0, uint32_t b1) {
    asm volatile(
        "mma.sync.aligned.m16n8k16.row.col.f32.f16.f16.f32 "
        "{%0,%1,%2,%3}, {%4,%5,%6,%7}, {%8,%9}, {%0,%1,%2,%3};"
        : "+f"(c[0]), "+f"(c[1]), "+f"(c[2]), "+f"(c[3])
        : "r"(a0), "r"(a1), "r"(a2), "r"(a3), "r"(b0), "r"(b1));
}

// ---- fp16 GEMM: C = relu(A16 @ Wt^T + b); A16 already ndst-scaled fp16 ----
#define S68 68

template <bool HALF_OUT>
__global__ __launch_bounds__(256)
void k_gemm_f16(const __half* __restrict__ A16, const __half* __restrict__ Wt,
                const float* __restrict__ bias, const float* __restrict__ nsrc,
                float* __restrict__ C, __half* __restrict__ C16, int N) {
    extern __shared__ uint32_t sh[];
    uint32_t* As = sh;              // 128 rows x 68 u32
    uint32_t* Ws = sh + 128 * S68;  // 128 cols x 68 u32

    const int tid = threadIdx.x;
    const int warp = tid >> 5;
    const int lane = tid & 31;
    const int g = lane >> 2;
    const int t = lane & 3;
    const int row0 = blockIdx.x * 128;

#pragma unroll
    for (int j = 0; j < 8; j++) {
        int f = tid + j * 256;
        int row = f >> 4;
        int c4 = f & 15;
        int grow = row0 + row;
        uint4 v = make_uint4(0u, 0u, 0u, 0u);
        if (grow < N) v = __ldg((const uint4*)(A16 + (size_t)grow * D) + c4);
        *(uint4*)&As[row * S68 + c4 * 4] = v;
    }
#pragma unroll
    for (int j = 0; j < 8; j++) {
        int f = tid + j * 256;
        int col = f >> 4;
        int c4 = f & 15;
        uint4 v = __ldg((const uint4*)(Wt + (size_t)col * D) + c4);
        *(uint4*)&Ws[col * S68 + c4 * 4] = v;
    }
    __syncthreads();

    float acc[16][4];
#pragma unroll
    for (int j = 0; j < 16; j++)
#pragma unroll
        for (int i = 0; i < 4; i++) acc[j][i] = 0.f;

    const int r = warp * 16;
#pragma unroll
    for (int ks = 0; ks < 8; ks++) {
        int ko = ks * 8 + t;
        uint32_t a0 = As[(r + g) * S68 + ko];
        uint32_t a1 = As[(r + g + 8) * S68 + ko];
        uint32_t a2 = As[(r + g) * S68 + ko + 4];
        uint32_t a3 = As[(r + g + 8) * S68 + ko + 4];
#pragma unroll
        for (int j = 0; j < 16; j++) {
            uint32_t b0 = Ws[(j * 8 + g) * S68 + ko];
            uint32_t b1 = Ws[(j * 8 + g) * S68 + ko + 4];
            mma_f16(acc[j], a0, a1, a2, a3, b0, b1);
        }
    }

    const int r1 = row0 + warp * 16 + g;
    const int r2 = r1 + 8;
    float ns1 = 1.f, ns2 = 1.f;
    if (HALF_OUT) {
        if (r1 < N) ns1 = __ldg(&nsrc[r1]);
        if (r2 < N) ns2 = __ldg(&nsrc[r2]);
    }
#pragma unroll
    for (int j = 0; j < 16; j++) {
        int col = j * 8 + 2 * t;
        float2 bv = *(const float2*)&bias[col];
        float2 o1, o2;
        o1.x = fmaxf(acc[j][0] + bv.x, 0.f);
        o1.y = fmaxf(acc[j][1] + bv.y, 0.f);
        o2.x = fmaxf(acc[j][2] + bv.x, 0.f);
        o2.y = fmaxf(acc[j][3] + bv.y, 0.f);
        if (HALF_OUT) {
            if (r1 < N) {
                __half2 h = __floats2half2_rn(o1.x * ns1, o1.y * ns1);
                *(__half2*)&C16[(size_t)r1 * D + col] = h;
            }
            if (r2 < N) {
                __half2 h = __floats2half2_rn(o2.x * ns2, o2.y * ns2);
                *(__half2*)&C16[(size_t)r2 * D + col] = h;
            }
        } else {
            if (r1 < N) *(float2*)&C[(size_t)r1 * D + col] = o1;
            if (r2 < N) *(float2*)&C[(size_t)r2 * D + col] = o2;
        }
    }
}

#define GEMM_SMEM (2 * 128 * S68 * 4)

extern "C" void kernel_launch(void* const* d_in, const int* in_sizes, int n_in,
                              void* d_out, int out_size) {
    const float* features = (const float*)d_in[0];
    const int* src = (const int*)d_in[1];
    const int* dst = (const int*)d_in[2];
    const float* W1 = (const float*)d_in[3];
    const float* b1 = (const float*)d_in[4];
    const float* W2 = (const float*)d_in[5];
    const float* b2 = (const float*)d_in[6];
    float* out = (float*)d_out;

    int N = in_sizes[0] / D;
    int E = in_sizes[1];

    int *cnt_out, *cnt_in, *row_start, *occ, *sorted_src;
    float *nsrc, *ndst;
    __half *hf16, *agg16, *w1t, *w2t;
    cudaGetSymbolAddress((void**)&cnt_out, g_cnt_out);
    cudaGetSymbolAddress((void**)&cnt_in, g_cnt_in);
    cudaGetSymbolAddress((void**)&row_start, g_row_start);
    cudaGetSymbolAddress((void**)&occ, g_occ);
    cudaGetSymbolAddress((void**)&sorted_src, g_sorted_src);
    cudaGetSymbolAddress((void**)&nsrc, g_norm_src);
    cudaGetSymbolAddress((void**)&ndst, g_norm_dst);
    cudaGetSymbolAddress((void**)&hf16, g_hf16);
    cudaGetSymbolAddress((void**)&agg16, g_agg16);
    cudaGetSymbolAddress((void**)&w1t, g_w1t);
    cudaGetSymbolAddress((void**)&w2t, g_w2t);

    cudaFuncSetAttribute(k_gemm_f16<true>, cudaFuncAttributeMaxDynamicSharedMemorySize, GEMM_SMEM);
    cudaFuncSetAttribute(k_gemm_f16<false>, cudaFuncAttributeMaxDynamicSharedMemorySize, GEMM_SMEM);

    const int ZB = 256;
    int nblkN = (N + ZB - 1) / ZB;
    int e4 = (E + 3) / 4;
    int nblkE4 = (e4 + ZB - 1) / ZB;
    int stride = nblkE4 * ZB;
    int f2h_blocks = (N * 32 + ZB - 1) / ZB;

    // prologue: 4 launches
    k_init<<<nblkN + 32, ZB>>>(cnt_out, cnt_in, N, nblkN, W1, W2, w1t, w2t);
    k_hist<<<nblkE4, ZB>>>(src, dst, cnt_out, cnt_in, occ, E, stride);
    k_scan<<<nblkN, SCAN_B>>>(cnt_out, cnt_in, row_start, nsrc, ndst, N);
    k_bucket_f2h<<<nblkE4 + f2h_blocks, ZB>>>(src, dst, occ, row_start, sorted_src,
                                              E, stride, nblkE4, features, cnt_out, hf16, N);

    int gath_blocks = (N * 16 + ZB - 1) / ZB;
    int gemm_blocks = (N + 127) / 128;

    // layer 1: gather (ndst-scaled fp16) -> agg16; fp16 GEMM -> h1 (fp16, nsrc-scaled)
    k_gather16<<<gath_blocks, ZB>>>(hf16, sorted_src, row_start, cnt_in, ndst, agg16, N);
    k_gemm_f16<true><<<gemm_blocks, 256, GEMM_SMEM>>>(agg16, w1t, b1, nsrc, nullptr, hf16, N);

    // layer 2: gather -> agg16; fp16 GEMM -> fp32 out
    k_gather16<<<gath_blocks, ZB>>>(hf16, sorted_src, row_start, cnt_in, ndst, agg16, N);
    k_gemm_f16<false><<<gemm_blocks, 256, GEMM_SMEM>>>(agg16, w2t, b2, nullptr, out, nullptr, N);
}

// round 17
// speedup vs baseline: 1.0273x; 1.0273x over previous
#include <cuda_runtime.h>
#include <cuda_fp16.h>
#include <cstdint>
#include <cstddef>

#define D 128
#define MAXN 50000
#define MAXE 600064
#define SCAN_B 256

// ---- scratch (allocation-free: __device__ globals) ----
__device__ int    g_cnt_out[MAXN];
__device__ int    g_cnt_in[MAXN];
__device__ float  g_norm_src[MAXN];
__device__ float  g_norm_dst[MAXN];
__device__ int    g_row_start[MAXN];
__device__ int    g_cursor[MAXN];
__device__ int    g_sorted_src[MAXE];
__device__ __half g_hf16[(size_t)MAXN * D];    // fp16 gather operand, PRE-SCALED by norm_src
__device__ __half g_agg16[(size_t)MAXN * D];   // fp16 aggregation buffer (ndst-scaled)
__device__ __half g_w1t[D * D];                // W1^T fp16 [col][k]
__device__ __half g_w2t[D * D];                // W2^T fp16 [col][k]

// ---- merged init: blocks [0,nblkN) zero counters; blocks [nblkN,nblkN+32) transpose W ----
__global__ void k_init(int* __restrict__ cnt_out, int* __restrict__ cnt_in, int N, int nblkN,
                       const float* __restrict__ W1, const float* __restrict__ W2,
                       __half* __restrict__ W1t, __half* __restrict__ W2t) {
    int b = blockIdx.x;
    int tid = threadIdx.x;
    if (b < nblkN) {
        int i = b * 256 + tid;
        if (i < N) { cnt_out[i] = 0; cnt_in[i] = 0; }
        return;
    }
    __shared__ float tile[32][33];
    int bb = b - nblkN;
    int z = bb >> 4, y = (bb >> 2) & 3, x = bb & 3;
    const float* W = z ? W2 : W1;
    __half* Wt = z ? W2t : W1t;
    int k0 = x * 32, c0 = y * 32;
    int tx = tid & 31, ty = tid >> 5;   // 32 x 8
#pragma unroll
    for (int i = 0; i < 4; i++) {
        int k = ty + i * 8;
        tile[k][tx] = __ldg(&W[(size_t)(k0 + k) * D + c0 + tx]);
    }
    __syncthreads();
#pragma unroll
    for (int i = 0; i < 4; i++) {
        int c = ty + i * 8;
        Wt[(size_t)(c0 + c) * D + k0 + tx] = __float2half_rn(tile[tx][c]);
    }
}

// ---- degree histogram: 4 consecutive edges per thread via int4 loads; REDG (no return) ----
__global__ void k_hist(const int* __restrict__ src, const int* __restrict__ dst,
                       int* __restrict__ cnt_out, int* __restrict__ cnt_in, int E) {
    int base = (blockIdx.x * blockDim.x + threadIdx.x) * 4;
    if (base + 3 < E) {
        int4 s = __ldg((const int4*)(src + base));
        int4 d = __ldg((const int4*)(dst + base));
        atomicAdd(&cnt_out[s.x], 1); atomicAdd(&cnt_in[d.x], 1);
        atomicAdd(&cnt_out[s.y], 1); atomicAdd(&cnt_in[d.y], 1);
        atomicAdd(&cnt_out[s.z], 1); atomicAdd(&cnt_in[d.z], 1);
        atomicAdd(&cnt_out[s.w], 1); atomicAdd(&cnt_in[d.w], 1);
    } else {
        for (int e = base; e < E; e++) {
            atomicAdd(&cnt_out[__ldg(&src[e])], 1);
            atomicAdd(&cnt_in[__ldg(&dst[e])], 1);
        }
    }
}

// ---- single-pass scan: per-block direct prefix re-read + in-block scan + norms ----
__global__ __launch_bounds__(SCAN_B)
void k_scan(const int* __restrict__ cnt_out, const int* __restrict__ cnt_in,
            int* __restrict__ row_start, int* __restrict__ cursor,
            float* __restrict__ nsrc, float* __restrict__ ndst, int N) {
    __shared__ int sh[SCAN_B];
    const int tid = threadIdx.x;
    const int b = blockIdx.x;

    int partial = 0;
    int lim = b * SCAN_B;
    for (int j = tid; j < lim; j += SCAN_B) partial += __ldg(&cnt_in[j]);
    sh[tid] = partial; __syncthreads();
#pragma unroll
    for (int off = 128; off > 0; off >>= 1) {
        if (tid < off) sh[tid] += sh[tid + off];
        __syncthreads();
    }
    int prefix = sh[0];
    __syncthreads();

    int i = b * SCAN_B + tid;
    int v = (i < N) ? __ldg(&cnt_in[i]) : 0;
    sh[tid] = v; __syncthreads();
#pragma unroll
    for (int off = 1; off < SCAN_B; off <<= 1) {
        int t = (tid >= off) ? sh[tid - off] : 0;
        __syncthreads();
        sh[tid] += t;
        __syncthreads();
    }
    if (i < N) {
        int r = prefix + sh[tid] - v;
        row_start[i] = r;
        cursor[i] = r;
        nsrc[i] = rsqrtf(fmaxf((float)__ldg(&cnt_out[i]), 1.f));
        ndst[i] = rsqrtf(fmaxf((float)v, 1.f));
    }
}

// ---- bucket edges by dst (atomic cursor), int4 edge loads ----
__global__ void k_bucket(const int* __restrict__ src, const int* __restrict__ dst,
                         int* __restrict__ cursor, int* __restrict__ sorted_src, int E) {
    int base = (blockIdx.x * blockDim.x + threadIdx.x) * 4;
    if (base + 3 < E) {
        int4 s = __ldg((const int4*)(src + base));
        int4 d = __ldg((const int4*)(dst + base));
        int p0 = atomicAdd(&cursor[d.x], 1);
        int p1 = atomicAdd(&cursor[d.y], 1);
        int p2 = atomicAdd(&cursor[d.z], 1);
        int p3 = atomicAdd(&cursor[d.w], 1);
        sorted_src[p0] = s.x;
        sorted_src[p1] = s.y;
        sorted_src[p2] = s.z;
        sorted_src[p3] = s.w;
    } else {
        for (int e = base; e < E; e++) {
            int pos = atomicAdd(&cursor[__ldg(&dst[e])], 1);
            sorted_src[pos] = __ldg(&src[e]);
        }
    }
}

// ---- fp16 feature mirror, pre-scaled by nsrc (recomputed from cnt_out); warp per row ----
__global__ void k_f2h(const float* __restrict__ features, const int* __restrict__ cnt_out,
                      __half* __restrict__ hf16, int N) {
    int row = (blockIdx.x * blockDim.x + threadIdx.x) >> 5;
    int lane = threadIdx.x & 31;
    if (row >= N) return;
    float ns = rsqrtf(fmaxf((float)__ldg(&cnt_out[row]), 1.f));
    float4 v = __ldg((const float4*)(features + (size_t)row * D) + lane);
    __half2 h0 = __floats2half2_rn(v.x * ns, v.y * ns);
    __half2 h1 = __floats2half2_rn(v.z * ns, v.w * ns);
    uint2 u;
    u.x = *(uint32_t*)&h0;
    u.y = *(uint32_t*)&h1;
    *((uint2*)(hf16 + (size_t)row * D) + lane) = u;
}

// ---- add 8 halves (uint4) into 8 fp32 accumulators ----
__device__ __forceinline__ void acc_add8(float* acc, uint4 u) {
    float2 p0 = __half22float2(*(__half2*)&u.x);
    float2 p1 = __half22float2(*(__half2*)&u.y);
    float2 p2 = __half22float2(*(__half2*)&u.z);
    float2 p3 = __half22float2(*(__half2*)&u.w);
    acc[0] += p0.x; acc[1] += p0.y;
    acc[2] += p1.x; acc[3] += p1.y;
    acc[4] += p2.x; acc[5] += p2.y;
    acc[6] += p3.x; acc[7] += p3.y;
}

// ---- atomic-free aggregation: HALF-WARP per dst node; applies ndst; fp16 out ----
__global__ void k_gather16(const __half* __restrict__ hf, const int* __restrict__ sorted_src,
                           const int* __restrict__ row_start, const int* __restrict__ cnt_in,
                           const float* __restrict__ ndst, __half* __restrict__ agg, int N) {
    int n = (blockIdx.x * blockDim.x + threadIdx.x) >> 4;
    int lane = threadIdx.x & 15;
    if (n >= N) return;
    int start = __ldg(&row_start[n]);
    int cnt = __ldg(&cnt_in[n]);
    float acc[8] = {0.f, 0.f, 0.f, 0.f, 0.f, 0.f, 0.f, 0.f};
    const int* sp = sorted_src + start;
    int j = 0;
    for (; j + 4 <= cnt; j += 4) {
        int s0 = __ldg(sp + j);
        int s1 = __ldg(sp + j + 1);
        int s2 = __ldg(sp + j + 2);
        int s3 = __ldg(sp + j + 3);
        uint4 u0 = __ldg((const uint4*)(hf + (size_t)s0 * D) + lane);
        uint4 u1 = __ldg((const uint4*)(hf + (size_t)s1 * D) + lane);
        uint4 u2 = __ldg((const uint4*)(hf + (size_t)s2 * D) + lane);
        uint4 u3 = __ldg((const uint4*)(hf + (size_t)s3 * D) + lane);
        acc_add8(acc, u0); acc_add8(acc, u1); acc_add8(acc, u2); acc_add8(acc, u3);
    }
    if (j + 2 <= cnt) {
        int s0 = __ldg(sp + j);
        int s1 = __ldg(sp + j + 1);
        uint4 u0 = __ldg((const uint4*)(hf + (size_t)s0 * D) + lane);
        uint4 u1 = __ldg((const uint4*)(hf + (size_t)s1 * D) + lane);
        acc_add8(acc, u0); acc_add8(acc, u1);
        j += 2;
    }
    if (j < cnt) {
        int s = __ldg(sp + j);
        uint4 u = __ldg((const uint4*)(hf + (size_t)s * D) + lane);
        acc_add8(acc, u);
    }
    float nd = __ldg(&ndst[n]);
    __half2 h0 = __floats2half2_rn(acc[0] * nd, acc[1] * nd);
    __half2 h1 = __floats2half2_rn(acc[2] * nd, acc[3] * nd);
    __half2 h2 = __floats2half2_rn(acc[4] * nd, acc[5] * nd);
    __half2 h3 = __floats2half2_rn(acc[6] * nd, acc[7] * nd);
    uint4 o;
    o.x = *(uint32_t*)&h0; o.y = *(uint32_t*)&h1;
    o.z = *(uint32_t*)&h2; o.w = *(uint32_t*)&h3;
    *((uint4*)(agg + (size_t)n * D) + lane) = o;
}

// ---- fp16 mma m16n8k16, fp32 accumulate ----
__device__ __forceinline__ void mma_f16(float* c, uint32_t a0, uint32_t a1,
                                        uint32_t a2, uint32_t a3,
                                        uint32_t b0, uint32_t b1) {
    asm volatile(
        "mma.sync.aligned.m16n8k16.row.col.f32.f16.f16.f32 "
        "{%0,%1,%2,%3}, {%4,%5,%6,%7}, {%8,%9}, {%0,%1,%2,%3};"
        : "+f"(c[0]), "+f"(c[1]), "+f"(c[2]), "+f"(c[3])
        : "r"(a0), "r"(a1), "r"(a2), "r"(a3), "r"(b0), "r"(b1));
}

// ---- fp16 GEMM: C = relu(A16 @ Wt^T + b); A16 already ndst-scaled fp16 ----
#define S68 68

template <bool HALF_OUT>
__global__ __launch_bounds__(256)
void k_gemm_f16(const __half* __restrict__ A16, const __half* __restrict__ Wt,
                const float* __restrict__ bias, const float* __restrict__ nsrc,
                float* __restrict__ C, __half* __restrict__ C16, int N) {
    extern __shared__ uint32_t sh[];
    uint32_t* As = sh;              // 128 rows x 68 u32
    uint32_t* Ws = sh + 128 * S68;  // 128 cols x 68 u32

    const int tid = threadIdx.x;
    const int warp = tid >> 5;
    const int lane = tid & 31;
    const int g = lane >> 2;
    const int t = lane & 3;
    const int row0 = blockIdx.x * 128;

#pragma unroll
    for (int j = 0; j < 8; j++) {
        int f = tid + j * 256;
        int row = f >> 4;
        int c4 = f & 15;
        int grow = row0 + row;
        uint4 v = make_uint4(0u, 0u, 0u, 0u);
        if (grow < N) v = __ldg((const uint4*)(A16 + (size_t)grow * D) + c4);
        *(uint4*)&As[row * S68 + c4 * 4] = v;
    }
#pragma unroll
    for (int j = 0; j < 8; j++) {
        int f = tid + j * 256;
        int col = f >> 4;
        int c4 = f & 15;
        uint4 v = __ldg((const uint4*)(Wt + (size_t)col * D) + c4);
        *(uint4*)&Ws[col * S68 + c4 * 4] = v;
    }
    __syncthreads();

    float acc[16][4];
#pragma unroll
    for (int j = 0; j < 16; j++)
#pragma unroll
        for (int i = 0; i < 4; i++) acc[j][i] = 0.f;

    const int r = warp * 16;
#pragma unroll
    for (int ks = 0; ks < 8; ks++) {
        int ko = ks * 8 + t;
        uint32_t a0 = As[(r + g) * S68 + ko];
        uint32_t a1 = As[(r + g + 8) * S68 + ko];
        uint32_t a2 = As[(r + g) * S68 + ko + 4];
        uint32_t a3 = As[(r + g + 8) * S68 + ko + 4];
#pragma unroll
        for (int j = 0; j < 16; j++) {
            uint32_t b0 = Ws[(j * 8 + g) * S68 + ko];
            uint32_t b1 = Ws[(j * 8 + g) * S68 + ko + 4];
            mma_f16(acc[j], a0, a1, a2, a3, b0, b1);
        }
    }

    const int r1 = row0 + warp * 16 + g;
    const int r2 = r1 + 8;
    float ns1 = 1.f, ns2 = 1.f;
    if (HALF_OUT) {
        if (r1 < N) ns1 = __ldg(&nsrc[r1]);
        if (r2 < N) ns2 = __ldg(&nsrc[r2]);
    }
#pragma unroll
    for (int j = 0; j < 16; j++) {
        int col = j * 8 + 2 * t;
        float2 bv = *(const float2*)&bias[col];
        float2 o1, o2;
        o1.x = fmaxf(acc[j][0] + bv.x, 0.f);
        o1.y = fmaxf(acc[j][1] + bv.y, 0.f);
        o2.x = fmaxf(acc[j][2] + bv.x, 0.f);
        o2.y = fmaxf(acc[j][3] + bv.y, 0.f);
        if (HALF_OUT) {
            if (r1 < N) {
                __half2 h = __floats2half2_rn(o1.x * ns1, o1.y * ns1);
                *(__half2*)&C16[(size_t)r1 * D + col] = h;
            }
            if (r2 < N) {
                __half2 h = __floats2half2_rn(o2.x * ns2, o2.y * ns2);
                *(__half2*)&C16[(size_t)r2 * D + col] = h;
            }
        } else {
            if (r1 < N) *(float2*)&C[(size_t)r1 * D + col] = o1;
            if (r2 < N) *(float2*)&C[(size_t)r2 * D + col] = o2;
        }
    }
}

#define GEMM_SMEM (2 * 128 * S68 * 4)

extern "C" void kernel_launch(void* const* d_in, const int* in_sizes, int n_in,
                              void* d_out, int out_size) {
    const float* features = (const float*)d_in[0];
    const int* src = (const int*)d_in[1];
    const int* dst = (const int*)d_in[2];
    const float* W1 = (const float*)d_in[3];
    const float* b1 = (const float*)d_in[4];
    const float* W2 = (const float*)d_in[5];
    const float* b2 = (const float*)d_in[6];
    float* out = (float*)d_out;

    int N = in_sizes[0] / D;
    int E = in_sizes[1];

    int *cnt_out, *cnt_in, *row_start, *cursor, *sorted_src;
    float *nsrc, *ndst;
    __half *hf16, *agg16, *w1t, *w2t;
    cudaGetSymbolAddress((void**)&cnt_out, g_cnt_out);
    cudaGetSymbolAddress((void**)&cnt_in, g_cnt_in);
    cudaGetSymbolAddress((void**)&row_start, g_row_start);
    cudaGetSymbolAddress((void**)&cursor, g_cursor);
    cudaGetSymbolAddress((void**)&sorted_src, g_sorted_src);
    cudaGetSymbolAddress((void**)&nsrc, g_norm_src);
    cudaGetSymbolAddress((void**)&ndst, g_norm_dst);
    cudaGetSymbolAddress((void**)&hf16, g_hf16);
    cudaGetSymbolAddress((void**)&agg16, g_agg16);
    cudaGetSymbolAddress((void**)&w1t, g_w1t);
    cudaGetSymbolAddress((void**)&w2t, g_w2t);

    // one-time host-side setup (no device memory): side stream + events + attrs
    static cudaStream_t s1 = nullptr;
    static cudaEvent_t ev_hist = nullptr, ev_f2h = nullptr;
    if (!s1) {
        cudaStreamCreateWithFlags(&s1, cudaStreamNonBlocking);
        cudaEventCreateWithFlags(&ev_hist, cudaEventDisableTiming);
        cudaEventCreateWithFlags(&ev_f2h, cudaEventDisableTiming);
        cudaFuncSetAttribute(k_gemm_f16<true>, cudaFuncAttributeMaxDynamicSharedMemorySize, GEMM_SMEM);
        cudaFuncSetAttribute(k_gemm_f16<false>, cudaFuncAttributeMaxDynamicSharedMemorySize, GEMM_SMEM);
    }
    cudaStream_t s0 = 0;  // legacy default stream (harness captures this)

    const int ZB = 256;
    int nblkN = (N + ZB - 1) / ZB;
    int nblkE4 = ((E + 3) / 4 + ZB - 1) / ZB;
    int f2h_blocks = (N * 32 + ZB - 1) / ZB;

    // prologue with fork/join: CSR chain on s0, f2h on s1
    k_init<<<nblkN + 32, ZB, 0, s0>>>(cnt_out, cnt_in, N, nblkN, W1, W2, w1t, w2t);
    k_hist<<<nblkE4, ZB, 0, s0>>>(src, dst, cnt_out, cnt_in, E);
    cudaEventRecord(ev_hist, s0);
    cudaStreamWaitEvent(s1, ev_hist, 0);
    // branch A (s0): scan + bucket
    k_scan<<<nblkN, SCAN_B, 0, s0>>>(cnt_out, cnt_in, row_start, cursor, nsrc, ndst, N);
    k_bucket<<<nblkE4, ZB, 0, s0>>>(src, dst, cursor, sorted_src, E);
    // branch B (s1): fp16 feature mirror
    k_f2h<<<f2h_blocks, ZB, 0, s1>>>(features, cnt_out, hf16, N);
    cudaEventRecord(ev_f2h, s1);
    cudaStreamWaitEvent(s0, ev_f2h, 0);

    int gath_blocks = (N * 16 + ZB - 1) / ZB;
    int gemm_blocks = (N + 127) / 128;

    // layer 1: gather (ndst-scaled fp16) -> agg16; fp16 GEMM -> h1 (fp16, nsrc-scaled)
    k_gather16<<<gath_blocks, ZB, 0, s0>>>(hf16, sorted_src, row_start, cnt_in, ndst, agg16, N);
    k_gemm_f16<true><<<gemm_blocks, 256, GEMM_SMEM, s0>>>(agg16, w1t, b1, nsrc, nullptr, hf16, N);

    // layer 2: gather -> agg16; fp16 GEMM -> fp32 out
    k_gather16<<<gath_blocks, ZB, 0, s0>>>(hf16, sorted_src, row_start, cnt_in, ndst, agg16, N);
    k_gemm_f16<false><<<gemm_blocks, 256, GEMM_SMEM, s0>>>(agg16, w2t, b2, nullptr, out, nullptr, N);
}